// round 2
// baseline (speedup 1.0000x reference)
#include <cuda_runtime.h>

// LGMLoss on GB300 — Round 2: labels are int32 (JAX x64-disabled downcast).
// Shapes fixed by the problem: B=2048, C=256, F=256.

#define B_BATCH 2048
#define C_CLS   256
#define F_DIM   256

#define ALPHA_F 0.1f
#define EPS_F   1e-8f

// GEMM tiling
#define BM 64
#define BN 64
#define BK 16
#define TSTRIDE 68   // smem row stride in floats

// __device__ scratch (allocation inside kernel_launch is forbidden)
__device__ float g_invv[C_CLS * F_DIM];     // 1/(v+eps)
__device__ float g_mv[C_CLS * F_DIM];       // -2*m/(v+eps)
__device__ float g_K[C_CLS];                // sum_f m^2/(v+eps)
__device__ float g_invden[C_CLS];           // 1/(det^2+eps)
__device__ float g_prob[B_BATCH * C_CLS];   // probability matrix

// ---------------------------------------------------------------------------
// Kernel A: per-class precompute. grid = C_CLS blocks, F_DIM threads.
// ---------------------------------------------------------------------------
__global__ void precompute_kernel(const float* __restrict__ means,
                                  const float* __restrict__ vars_) {
    int c = blockIdx.x;
    int f = threadIdx.x;
    float v  = vars_[c * F_DIM + f];
    float iv = 1.0f / (v + EPS_F);
    float m  = means[c * F_DIM + f];
    g_invv[c * F_DIM + f] = iv;
    g_mv[c * F_DIM + f]   = -2.0f * m * iv;

    __shared__ float ssum[F_DIM];
    __shared__ float sprod[F_DIM];
    ssum[f]  = m * m * iv;
    sprod[f] = v;
    __syncthreads();
    #pragma unroll
    for (int s = F_DIM / 2; s > 0; s >>= 1) {
        if (f < s) {
            ssum[f]  += ssum[f + s];
            sprod[f] *= sprod[f + s];
        }
        __syncthreads();
    }
    if (f == 0) {
        g_K[c] = ssum[0];
        float det = sprod[0];
        g_invden[c] = 1.0f / (det * det + EPS_F);
    }
}

// ---------------------------------------------------------------------------
// Kernel B: fused distance GEMM + prob epilogue.
// D[b,c] = 0.5*( feat2 @ invv^T + feat @ (-2 m invv)^T + K[c] )
// p[b,c] = expf(-D * (c==label ? 1.1 : 1)) * invden[c]
// grid = (B/BM, C/BN), 256 threads, 4x4 microtile, dual accumulators.
// ---------------------------------------------------------------------------
__global__ __launch_bounds__(256) void dist_prob_kernel(
    const float* __restrict__ feat,
    const int* __restrict__ labels) {
    __shared__ float sA [BK * TSTRIDE];
    __shared__ float sA2[BK * TSTRIDE];
    __shared__ float sBi[BK * TSTRIDE];
    __shared__ float sBm[BK * TSTRIDE];

    const int tid   = threadIdx.x;
    const int bRow0 = blockIdx.x * BM;
    const int cCol0 = blockIdx.y * BN;
    const int tm    = tid >> 4;    // 0..15 -> rows tm*4..tm*4+3
    const int tn    = tid & 15;    // 0..15 -> cols tn*4..tn*4+3

    float acc1[4][4] = {};
    float acc2[4][4] = {};

    for (int k0 = 0; k0 < F_DIM; k0 += BK) {
        // cooperative tile load: 64 rows x 16 k, 4 elems/thread per array
        #pragma unroll
        for (int it = 0; it < 4; it++) {
            int lin = tid + it * 256;
            int r   = lin >> 4;     // 0..63
            int kk  = lin & 15;     // 0..15
            float a = feat[(bRow0 + r) * F_DIM + k0 + kk];
            sA [kk * TSTRIDE + r] = a;
            sA2[kk * TSTRIDE + r] = a * a;
            sBi[kk * TSTRIDE + r] = g_invv[(cCol0 + r) * F_DIM + k0 + kk];
            sBm[kk * TSTRIDE + r] = g_mv  [(cCol0 + r) * F_DIM + k0 + kk];
        }
        __syncthreads();

        #pragma unroll
        for (int kk = 0; kk < BK; kk++) {
            float4 ra  = *(const float4*)&sA [kk * TSTRIDE + tm * 4];
            float4 ra2 = *(const float4*)&sA2[kk * TSTRIDE + tm * 4];
            float4 rbi = *(const float4*)&sBi[kk * TSTRIDE + tn * 4];
            float4 rbm = *(const float4*)&sBm[kk * TSTRIDE + tn * 4];
            float A [4] = {ra.x,  ra.y,  ra.z,  ra.w};
            float A2[4] = {ra2.x, ra2.y, ra2.z, ra2.w};
            float Bi[4] = {rbi.x, rbi.y, rbi.z, rbi.w};
            float Bm[4] = {rbm.x, rbm.y, rbm.z, rbm.w};
            #pragma unroll
            for (int i = 0; i < 4; i++) {
                #pragma unroll
                for (int j = 0; j < 4; j++) {
                    acc1[i][j] = fmaf(A2[i], Bi[j], acc1[i][j]);
                    acc2[i][j] = fmaf(A [i], Bm[j], acc2[i][j]);
                }
            }
        }
        __syncthreads();
    }

    // epilogue
    #pragma unroll
    for (int i = 0; i < 4; i++) {
        int b = bRow0 + tm * 4 + i;
        int lbl = labels[b];
        #pragma unroll
        for (int j = 0; j < 4; j++) {
            int c = cCol0 + tn * 4 + j;
            float d = 0.5f * (acc1[i][j] + acc2[i][j] + g_K[c]);
            if (c == lbl) d *= (1.0f + ALPHA_F);
            g_prob[b * C_CLS + c] = expf(-d) * g_invden[c];
        }
    }
}

// ---------------------------------------------------------------------------
// Kernel C: per-row loss. One warp per batch row.
// grid = B/8 blocks, 256 threads (8 warps).
// ---------------------------------------------------------------------------
__global__ void loss_kernel(const int* __restrict__ labels,
                            float* __restrict__ out) {
    int b    = blockIdx.x * 8 + (threadIdx.x >> 5);
    int lane = threadIdx.x & 31;
    const float* row = g_prob + (size_t)b * C_CLS;
    float s = 0.0f;
    #pragma unroll
    for (int c = lane; c < C_CLS; c += 32) s += row[c];
    #pragma unroll
    for (int o = 16; o > 0; o >>= 1) s += __shfl_xor_sync(0xffffffffu, s, o);
    if (lane == 0) {
        int lbl = labels[b];
        // defensive clamp: valid labels are [0, C); avoids OOB if dtype shifts
        lbl = (lbl < 0) ? 0 : (lbl >= C_CLS ? C_CLS - 1 : lbl);
        float pl = row[lbl];
        out[b] = -logf(pl / (s + EPS_F) + EPS_F);
    }
}

// ---------------------------------------------------------------------------
extern "C" void kernel_launch(void* const* d_in, const int* in_sizes, int n_in,
                              void* d_out, int out_size) {
    const float* feat   = (const float*)d_in[0];
    const int*   labels = (const int*)d_in[1];
    const float* means  = (const float*)d_in[2];
    const float* vars_  = (const float*)d_in[3];
    float* out = (float*)d_out;

    precompute_kernel<<<C_CLS, F_DIM>>>(means, vars_);

    dim3 grid(B_BATCH / BM, C_CLS / BN);
    dist_prob_kernel<<<grid, 256>>>(feat, labels);

    loss_kernel<<<B_BATCH / 8, 256>>>(labels, out);

    // passthrough outputs: (loss[B], means[C,F], vars[C,F])
    cudaMemcpyAsync(out + B_BATCH, means,
                    (size_t)C_CLS * F_DIM * sizeof(float),
                    cudaMemcpyDeviceToDevice, 0);
    cudaMemcpyAsync(out + B_BATCH + C_CLS * F_DIM, vars_,
                    (size_t)C_CLS * F_DIM * sizeof(float),
                    cudaMemcpyDeviceToDevice, 0);
}

// round 4
// speedup vs baseline: 2.2721x; 2.2721x over previous
#include <cuda_runtime.h>
#include <cuda_bf16.h>
#include <cstdint>

// LGMLoss on GB300 — Round 4: mma.sync (HMMA) bf16 GEMM, fully fused.
// tcgen05 is unavailable (harness emits base-target sm_103 PTX).
// D[2048x256] = A'[2048x512] @ B'[256x512]^T, bf16 in / fp32 acc.

#define B_BATCH 2048
#define C_CLS   256
#define F_DIM   256
#define ALPHA_F 0.1f
#define EPS_F   1e-8f

#define KC     64      // bf16 k-elems per chunk (32 features)
#define NCHUNK 8       // 512 / 64
#define ASTRB  144     // smem row stride bytes (KC*2 + 16 pad) -> conflict-free ldmatrix

// ---------------- device scratch ----------------
__device__ __nv_bfloat162 g_Bbf[C_CLS * F_DIM];  // [256][256] pairs (iv, -2m*iv)
__device__ float g_K[C_CLS];
__device__ float g_invden[C_CLS];

// ---------------- helpers ----------------
__device__ __forceinline__ uint32_t smem_u32(const void* p) {
    uint32_t a;
    asm("{ .reg .u64 t; cvta.to.shared.u64 t, %1; cvt.u32.u64 %0, t; }"
        : "=r"(a) : "l"(p));
    return a;
}

__device__ __forceinline__ void ldmatrix_x4(uint32_t* r, uint32_t addr) {
    asm volatile("ldmatrix.sync.aligned.m8n8.x4.shared.b16 {%0,%1,%2,%3}, [%4];"
                 : "=r"(r[0]), "=r"(r[1]), "=r"(r[2]), "=r"(r[3]) : "r"(addr));
}

__device__ __forceinline__ void mma16816(float* d, const uint32_t* a,
                                         uint32_t b0, uint32_t b1) {
    asm volatile(
        "mma.sync.aligned.m16n8k16.row.col.f32.bf16.bf16.f32 "
        "{%0,%1,%2,%3}, {%4,%5,%6,%7}, {%8,%9}, {%0,%1,%2,%3};"
        : "+f"(d[0]), "+f"(d[1]), "+f"(d[2]), "+f"(d[3])
        : "r"(a[0]), "r"(a[1]), "r"(a[2]), "r"(a[3]), "r"(b0), "r"(b1));
}

__device__ __forceinline__ uint32_t pack_pair(float x) {
    __nv_bfloat162 p = __floats2bfloat162_rn(x * x, x);   // (x^2, x)
    return *(uint32_t*)&p;
}

// ---------------------------------------------------------------------------
// Kernel 1: per-class precompute -> B' pairs, K[c], invden[c].
// grid = 256, block = 256.
// ---------------------------------------------------------------------------
__global__ __launch_bounds__(256) void precompute_kernel(
    const float* __restrict__ means,
    const float* __restrict__ vars_) {
    int c = blockIdx.x;
    int t = threadIdx.x;
    float v = vars_[c * F_DIM + t];
    float m = means[c * F_DIM + t];
    float iv = 1.0f / (v + EPS_F);
    g_Bbf[c * F_DIM + t] = __floats2bfloat162_rn(iv, -2.0f * m * iv);

    float ks = m * m * iv;
    float pr = v;
    #pragma unroll
    for (int o = 16; o > 0; o >>= 1) {
        ks += __shfl_xor_sync(0xffffffffu, ks, o);
        pr *= __shfl_xor_sync(0xffffffffu, pr, o);
    }
    __shared__ float wsum[8], wprod[8];
    int w = t >> 5, l = t & 31;
    if (l == 0) { wsum[w] = ks; wprod[w] = pr; }
    __syncthreads();
    if (t == 0) {
        float K = 0.0f, det = 1.0f;
        #pragma unroll
        for (int i = 0; i < 8; i++) { K += wsum[i]; det *= wprod[i]; }
        g_K[c] = K;
        g_invden[c] = 1.0f / (det * det + EPS_F);
    }
}

// ---------------------------------------------------------------------------
// Kernel 2: fused bf16 HMMA GEMM + prob/loss epilogue.
// grid = 32 CTAs (M=64 rows each, N=256 all classes), 256 threads (8 warps).
// Warp grid 2(M) x 4(N); warp tile 32x64; mma m16n8k16.
// Dynamic smem (bytes):
//   0: sK[256] | 1024: sInv[256] | 2048: sPartS[4][64] | 3072: sPartP[4][64]
//   4096: A bufs 2 x 9216 (64 rows x 144B) | 22528: B bufs 2 x 36864 (256 x 144B)
// ---------------------------------------------------------------------------
#define SM_KOFF 0
#define SM_IOFF 1024
#define SM_SP   2048
#define SM_PP   3072
#define SM_A    4096
#define SM_B    22528
#define SMEM_TOTAL 96256

__global__ __launch_bounds__(256, 1) void lgm_gemm_kernel(
    const float* __restrict__ feat,
    const int* __restrict__ labels,
    float* __restrict__ out) {
    extern __shared__ char smem[];
    const int tid  = threadIdx.x;
    const int wid  = tid >> 5;
    const int lane = tid & 31;
    const int wm   = wid >> 2;            // 0..1  (M)
    const int wn   = wid & 3;             // 0..3  (N)
    const int bRow0 = blockIdx.x * 64;

    float* sK   = (float*)(smem + SM_KOFF);
    float* sInv = (float*)(smem + SM_IOFF);
    float* sPS  = (float*)(smem + SM_SP);
    float* sPP  = (float*)(smem + SM_PP);
    sK[tid]   = g_K[tid];
    sInv[tid] = g_invden[tid];

    const float4* featv = (const float4*)feat;   // rows of 64 float4
    const uint4*  Bg    = (const uint4*)g_Bbf;   // rows of 64 uint4 (1KB)

    float acc[2][8][4] = {};
    float4 aF[2];
    uint4  bF[8];

    // fetch chunk ci into registers
    auto fetch = [&](int ci) {
        #pragma unroll
        for (int u = 0; u < 2; u++) {
            int seg = tid * 2 + u;                // 0..511
            int r = seg >> 3, s = seg & 7;
            aF[u] = featv[(bRow0 + r) * 64 + ci * 8 + s];
        }
        #pragma unroll
        for (int u = 0; u < 8; u++) {
            int seg = tid + u * 256;              // 0..2047
            int r = seg >> 3, s = seg & 7;
            bF[u] = Bg[r * 64 + ci * 8 + s];
        }
    };
    // store registers into smem buffer `buf` (with bf16 pair conversion for A)
    auto store = [&](int buf) {
        char* sA = smem + SM_A + buf * 9216;
        char* sB = smem + SM_B + buf * 36864;
        #pragma unroll
        for (int u = 0; u < 2; u++) {
            int seg = tid * 2 + u;
            int r = seg >> 3, s = seg & 7;
            float4 v = aF[u];
            uint4 w;
            w.x = pack_pair(v.x); w.y = pack_pair(v.y);
            w.z = pack_pair(v.z); w.w = pack_pair(v.w);
            *(uint4*)(sA + r * ASTRB + s * 16) = w;
        }
        #pragma unroll
        for (int u = 0; u < 8; u++) {
            int seg = tid + u * 256;
            int r = seg >> 3, s = seg & 7;
            *(uint4*)(sB + r * ASTRB + s * 16) = bF[u];
        }
    };

    fetch(0);
    store(0);
    __syncthreads();

    #pragma unroll 1
    for (int ci = 0; ci < NCHUNK; ci++) {
        const int buf = ci & 1;
        if (ci + 1 < NCHUNK) fetch(ci + 1);

        const uint32_t sAu = smem_u32(smem + SM_A + buf * 9216);
        const uint32_t sBu = smem_u32(smem + SM_B + buf * 36864);
        #pragma unroll
        for (int ks = 0; ks < 4; ks++) {          // 4 x k16 per chunk
            uint32_t a[2][4], b[4][4];
            #pragma unroll
            for (int mt = 0; mt < 2; mt++) {
                uint32_t addr = sAu
                    + (uint32_t)(wm * 32 + mt * 16 + (lane & 15)) * ASTRB
                    + (uint32_t)(ks * 32 + ((lane >> 4) & 1) * 16);
                ldmatrix_x4(a[mt], addr);
            }
            #pragma unroll
            for (int nt16 = 0; nt16 < 4; nt16++) {
                uint32_t addr = sBu
                    + (uint32_t)(wn * 64 + nt16 * 16 + (lane & 7)
                                 + ((lane >> 4) & 1) * 8) * ASTRB
                    + (uint32_t)(ks * 32 + ((lane >> 3) & 1) * 16);
                ldmatrix_x4(b[nt16], addr);
            }
            #pragma unroll
            for (int mt = 0; mt < 2; mt++) {
                #pragma unroll
                for (int nt = 0; nt < 8; nt++) {
                    mma16816(acc[mt][nt], a[mt],
                             b[nt >> 1][(nt & 1) * 2],
                             b[nt >> 1][(nt & 1) * 2 + 1]);
                }
            }
        }
        if (ci + 1 < NCHUNK) store(buf ^ 1);
        __syncthreads();
    }

    // ---------------- epilogue ----------------
    // D frag: d0/d1 -> row base+lane/4, cols c0/c0+1; d2/d3 -> row +8.
    float sums[2][2] = {{0.f, 0.f}, {0.f, 0.f}};
    float pls [2][2] = {{0.f, 0.f}, {0.f, 0.f}};
    int lbls[2][2];
    #pragma unroll
    for (int mt = 0; mt < 2; mt++) {
        int rA = bRow0 + wm * 32 + mt * 16 + (lane >> 2);
        lbls[mt][0] = labels[rA];
        lbls[mt][1] = labels[rA + 8];
    }
    #pragma unroll
    for (int mt = 0; mt < 2; mt++) {
        #pragma unroll
        for (int nt = 0; nt < 8; nt++) {
            int c0 = wn * 64 + nt * 8 + (lane & 3) * 2;
            int c1 = c0 + 1;
            float k0 = sK[c0], k1 = sK[c1];
            float i0 = sInv[c0], i1 = sInv[c1];
            #pragma unroll
            for (int h = 0; h < 2; h++) {          // h=0: rows low (d0,d1); h=1: +8 (d2,d3)
                int lbl = lbls[mt][h];
                float d0 = 0.5f * (acc[mt][nt][h * 2 + 0] + k0);
                float d1 = 0.5f * (acc[mt][nt][h * 2 + 1] + k1);
                if (c0 == lbl) d0 *= (1.0f + ALPHA_F);
                if (c1 == lbl) d1 *= (1.0f + ALPHA_F);
                float p0 = __expf(-d0) * i0;
                float p1 = __expf(-d1) * i1;
                sums[mt][h] += p0 + p1;
                if (c0 == lbl) pls[mt][h] += p0;
                if (c1 == lbl) pls[mt][h] += p1;
            }
        }
    }
    // reduce over the 4 lanes sharing a row (lane bits 0..1)
    #pragma unroll
    for (int o = 1; o < 4; o <<= 1) {
        #pragma unroll
        for (int mt = 0; mt < 2; mt++) {
            #pragma unroll
            for (int h = 0; h < 2; h++) {
                sums[mt][h] += __shfl_xor_sync(0xffffffffu, sums[mt][h], o);
                pls [mt][h] += __shfl_xor_sync(0xffffffffu, pls [mt][h], o);
            }
        }
    }
    if ((lane & 3) == 0) {
        #pragma unroll
        for (int mt = 0; mt < 2; mt++) {
            #pragma unroll
            for (int h = 0; h < 2; h++) {
                int rloc = wm * 32 + mt * 16 + (lane >> 2) + h * 8;
                sPS[wn * 64 + rloc] = sums[mt][h];
                sPP[wn * 64 + rloc] = pls[mt][h];
            }
        }
    }
    __syncthreads();
    if (tid < 64) {
        float s = 0.f, pl = 0.f;
        #pragma unroll
        for (int w = 0; w < 4; w++) {
            s  += sPS[w * 64 + tid];
            pl += sPP[w * 64 + tid];
        }
        out[bRow0 + tid] = -logf(pl / (s + EPS_F) + EPS_F);
    }
}

// ---------------------------------------------------------------------------
extern "C" void kernel_launch(void* const* d_in, const int* in_sizes, int n_in,
                              void* d_out, int out_size) {
    const float* feat   = (const float*)d_in[0];
    const int*   labels = (const int*)d_in[1];
    const float* means  = (const float*)d_in[2];
    const float* vars_  = (const float*)d_in[3];
    float* out = (float*)d_out;

    cudaFuncSetAttribute(lgm_gemm_kernel,
                         cudaFuncAttributeMaxDynamicSharedMemorySize, SMEM_TOTAL);

    precompute_kernel<<<C_CLS, 256>>>(means, vars_);
    lgm_gemm_kernel<<<B_BATCH / 64, 256, SMEM_TOTAL>>>(feat, labels, out);

    // passthrough outputs: (loss[B], means[C,F], vars[C,F])
    cudaMemcpyAsync(out + B_BATCH, means,
                    (size_t)C_CLS * F_DIM * sizeof(float),
                    cudaMemcpyDeviceToDevice, 0);
    cudaMemcpyAsync(out + B_BATCH + C_CLS * F_DIM, vars_,
                    (size_t)C_CLS * F_DIM * sizeof(float),
                    cudaMemcpyDeviceToDevice, 0);
}

// round 5
// speedup vs baseline: 3.2716x; 1.4399x over previous
#include <cuda_runtime.h>
#include <cuda_bf16.h>
#include <cstdint>

// LGMLoss on GB300 — Round 5: HMMA GEMM, 128 CTAs (BM=16, N=256 in-CTA),
// cp.async B pipeline, fully fused loss, passthrough folded into precompute.
// D[2048x256] = A'[2048x512] @ B'[256x512]^T, bf16 in / fp32 acc.

#define B_BATCH 2048
#define C_CLS   256
#define F_DIM   256
#define ALPHA_F 0.1f
#define EPS_F   1e-8f

#define BM      16
#define KC      128            // bf16 k-elems per chunk (64 features); 4 chunks
#define NCHUNK  4
#define STR     272            // smem row stride bytes (256 + 16 pad)

// ---------------- device scratch ----------------
__device__ __nv_bfloat162 g_Bbf[C_CLS * F_DIM];  // [256][256] pairs (iv, -2m*iv)
__device__ float g_K[C_CLS];
__device__ float g_invden[C_CLS];

// ---------------- helpers ----------------
__device__ __forceinline__ uint32_t smem_u32(const void* p) {
    uint32_t a;
    asm("{ .reg .u64 t; cvta.to.shared.u64 t, %1; cvt.u32.u64 %0, t; }"
        : "=r"(a) : "l"(p));
    return a;
}
__device__ __forceinline__ void ldmatrix_x4(uint32_t* r, uint32_t addr) {
    asm volatile("ldmatrix.sync.aligned.m8n8.x4.shared.b16 {%0,%1,%2,%3}, [%4];"
                 : "=r"(r[0]), "=r"(r[1]), "=r"(r[2]), "=r"(r[3]) : "r"(addr));
}
__device__ __forceinline__ void mma16816(float* d, const uint32_t* a,
                                         uint32_t b0, uint32_t b1) {
    asm volatile(
        "mma.sync.aligned.m16n8k16.row.col.f32.bf16.bf16.f32 "
        "{%0,%1,%2,%3}, {%4,%5,%6,%7}, {%8,%9}, {%0,%1,%2,%3};"
        : "+f"(d[0]), "+f"(d[1]), "+f"(d[2]), "+f"(d[3])
        : "r"(a[0]), "r"(a[1]), "r"(a[2]), "r"(a[3]), "r"(b0), "r"(b1));
}
__device__ __forceinline__ void cp_async16(uint32_t saddr, const void* gaddr) {
    asm volatile("cp.async.cg.shared.global [%0], [%1], 16;"
                 :: "r"(saddr), "l"(gaddr) : "memory");
}
__device__ __forceinline__ void cp_commit() {
    asm volatile("cp.async.commit_group;" ::: "memory");
}
__device__ __forceinline__ void cp_wait0() {
    asm volatile("cp.async.wait_group 0;" ::: "memory");
}
__device__ __forceinline__ uint32_t pack_pair(float x) {
    __nv_bfloat162 p = __floats2bfloat162_rn(x * x, x);   // (x^2, x)
    return *(uint32_t*)&p;
}

// ---------------------------------------------------------------------------
// Kernel 1: per-class precompute + means/vars passthrough copy.
// grid = 256, block = 256.
// ---------------------------------------------------------------------------
__global__ __launch_bounds__(256) void precompute_kernel(
    const float* __restrict__ means,
    const float* __restrict__ vars_,
    float* __restrict__ out) {
    int c = blockIdx.x;
    int t = threadIdx.x;
    float v = vars_[c * F_DIM + t];
    float m = means[c * F_DIM + t];
    float iv = 1.0f / (v + EPS_F);
    g_Bbf[c * F_DIM + t] = __floats2bfloat162_rn(iv, -2.0f * m * iv);
    // passthrough outputs (replaces two cudaMemcpyAsync nodes)
    out[B_BATCH + c * F_DIM + t] = m;
    out[B_BATCH + C_CLS * F_DIM + c * F_DIM + t] = v;

    float ks = m * m * iv;
    float pr = v;
    #pragma unroll
    for (int o = 16; o > 0; o >>= 1) {
        ks += __shfl_xor_sync(0xffffffffu, ks, o);
        pr *= __shfl_xor_sync(0xffffffffu, pr, o);
    }
    __shared__ float wsum[8], wprod[8];
    int w = t >> 5, l = t & 31;
    if (l == 0) { wsum[w] = ks; wprod[w] = pr; }
    __syncthreads();
    if (t == 0) {
        float K = 0.0f, det = 1.0f;
        #pragma unroll
        for (int i = 0; i < 8; i++) { K += wsum[i]; det *= wprod[i]; }
        g_K[c] = K;
        g_invden[c] = 1.0f / (det * det + EPS_F);
    }
}

// ---------------------------------------------------------------------------
// Kernel 2: fused bf16 HMMA GEMM + prob/loss epilogue.
// grid = 128 CTAs (BM=16 rows, all 256 cols), 256 threads (8 warps).
// Warp w covers cols w*32..w*32+31, rows 0..15. mma m16n8k16, 4 per k-step.
// Dynamic smem (bytes):
//   0: sK[256] | 1024: sInv[256] | 2048: sPS[128]+sPP[128] (1KB)
//   4096: A bufs 2 x 4352 (16 rows x 272B)
//   12800: B bufs 2 x 69632 (256 rows x 272B)   total 152064
// ---------------------------------------------------------------------------
#define SM_KOFF 0
#define SM_IOFF 1024
#define SM_RED  2048
#define SM_A    4096
#define SM_B    12800
#define A_BUFSZ 4352
#define B_BUFSZ 69632
#define SMEM_TOTAL 152064

__global__ __launch_bounds__(256, 1) void lgm_gemm_kernel(
    const float* __restrict__ feat,
    const int* __restrict__ labels,
    float* __restrict__ out) {
    extern __shared__ char smem[];
    const int tid  = threadIdx.x;
    const int wid  = tid >> 5;
    const int lane = tid & 31;
    const int bRow0 = blockIdx.x * BM;

    float* sK   = (float*)(smem + SM_KOFF);
    float* sInv = (float*)(smem + SM_IOFF);
    float* sPS  = (float*)(smem + SM_RED);          // [16 rows][8 warps]
    float* sPP  = sPS + 128;
    sK[tid]   = g_K[tid];
    sInv[tid] = g_invden[tid];

    const float4* featv = (const float4*)feat;      // 64 float4 per row
    const uint4*  Bg    = (const uint4*)g_Bbf;      // 64 uint4 per row
    const uint32_t sbase = smem_u32(smem);

    // A fetch: 256 segs (16 rows x 16), 1 per thread
    const int ar = tid >> 4, as = tid & 15;
    float4 aReg;
    auto fetchA = [&](int ci) {
        aReg = featv[(bRow0 + ar) * 64 + ci * 16 + as];
    };
    auto storeA = [&](int buf) {
        uint4 w;
        w.x = pack_pair(aReg.x); w.y = pack_pair(aReg.y);
        w.z = pack_pair(aReg.z); w.w = pack_pair(aReg.w);
        *(uint4*)(smem + SM_A + buf * A_BUFSZ + ar * STR + as * 16) = w;
    };
    // B fetch via cp.async: 4096 segs (256 rows x 16), 16 per thread
    auto issueB = [&](int ci) {
        uint32_t dst = sbase + SM_B + (ci & 1) * B_BUFSZ;
        #pragma unroll
        for (int u = 0; u < 16; u++) {
            int g = tid + u * 256;
            int r = g >> 4, s = g & 15;
            cp_async16(dst + r * STR + s * 16, Bg + r * 64 + ci * 16 + s);
        }
        cp_commit();
    };

    float acc[4][4] = {};

    fetchA(0);
    issueB(0);
    storeA(0);

    #pragma unroll
    for (int ci = 0; ci < NCHUNK; ci++) {
        const int buf = ci & 1;
        cp_wait0();
        __syncthreads();
        if (ci + 1 < NCHUNK) { issueB(ci + 1); fetchA(ci + 1); }

        const uint32_t sAu = sbase + SM_A + buf * A_BUFSZ;
        const uint32_t sBu = sbase + SM_B + buf * B_BUFSZ;
        #pragma unroll
        for (int ks = 0; ks < 8; ks++) {            // 8 x k16 per chunk
            uint32_t a[4], b[2][4];
            ldmatrix_x4(a, sAu + (uint32_t)(lane & 15) * STR
                           + (uint32_t)(ks * 32 + ((lane >> 4) & 1) * 16));
            #pragma unroll
            for (int nt16 = 0; nt16 < 2; nt16++) {
                uint32_t addr = sBu
                    + (uint32_t)(wid * 32 + nt16 * 16 + (lane & 7)
                                 + ((lane >> 4) & 1) * 8) * STR
                    + (uint32_t)(ks * 32 + ((lane >> 3) & 1) * 16);
                ldmatrix_x4(b[nt16], addr);
            }
            #pragma unroll
            for (int nt = 0; nt < 4; nt++) {
                mma16816(acc[nt], a, b[nt >> 1][(nt & 1) * 2],
                                     b[nt >> 1][(nt & 1) * 2 + 1]);
            }
        }
        if (ci + 1 < NCHUNK) storeA(buf ^ 1);
        __syncthreads();
    }

    // ---------------- epilogue ----------------
    // acc[nt][0..1]: row r0=lane>>2, cols c0,c0+1; acc[nt][2..3]: row r0+8.
    const int r0 = lane >> 2;
    const int lbl0 = labels[bRow0 + r0];
    const int lbl1 = labels[bRow0 + r0 + 8];
    float s0 = 0.f, s1 = 0.f, pl0 = 0.f, pl1 = 0.f;
    #pragma unroll
    for (int nt = 0; nt < 4; nt++) {
        int c0 = wid * 32 + nt * 8 + (lane & 3) * 2;
        int c1 = c0 + 1;
        float k0 = sK[c0], k1 = sK[c1];
        float i0 = sInv[c0], i1 = sInv[c1];
        {
            float d0 = 0.5f * (acc[nt][0] + k0);
            float d1 = 0.5f * (acc[nt][1] + k1);
            if (c0 == lbl0) d0 *= (1.0f + ALPHA_F);
            if (c1 == lbl0) d1 *= (1.0f + ALPHA_F);
            float p0 = __expf(-d0) * i0;
            float p1 = __expf(-d1) * i1;
            s0 += p0 + p1;
            if (c0 == lbl0) pl0 += p0;
            if (c1 == lbl0) pl0 += p1;
        }
        {
            float d0 = 0.5f * (acc[nt][2] + k0);
            float d1 = 0.5f * (acc[nt][3] + k1);
            if (c0 == lbl1) d0 *= (1.0f + ALPHA_F);
            if (c1 == lbl1) d1 *= (1.0f + ALPHA_F);
            float p0 = __expf(-d0) * i0;
            float p1 = __expf(-d1) * i1;
            s1 += p0 + p1;
            if (c0 == lbl1) pl1 += p0;
            if (c1 == lbl1) pl1 += p1;
        }
    }
    #pragma unroll
    for (int o = 1; o < 4; o <<= 1) {
        s0  += __shfl_xor_sync(0xffffffffu, s0, o);
        s1  += __shfl_xor_sync(0xffffffffu, s1, o);
        pl0 += __shfl_xor_sync(0xffffffffu, pl0, o);
        pl1 += __shfl_xor_sync(0xffffffffu, pl1, o);
    }
    if ((lane & 3) == 0) {
        sPS[r0 * 8 + wid]       = s0;
        sPS[(r0 + 8) * 8 + wid] = s1;
        sPP[r0 * 8 + wid]       = pl0;
        sPP[(r0 + 8) * 8 + wid] = pl1;
    }
    __syncthreads();
    if (tid < BM) {
        float s = 0.f, pl = 0.f;
        #pragma unroll
        for (int w = 0; w < 8; w++) {
            s  += sPS[tid * 8 + w];
            pl += sPP[tid * 8 + w];
        }
        out[bRow0 + tid] = -logf(pl / (s + EPS_F) + EPS_F);
    }
}

// ---------------------------------------------------------------------------
extern "C" void kernel_launch(void* const* d_in, const int* in_sizes, int n_in,
                              void* d_out, int out_size) {
    const float* feat   = (const float*)d_in[0];
    const int*   labels = (const int*)d_in[1];
    const float* means  = (const float*)d_in[2];
    const float* vars_  = (const float*)d_in[3];
    float* out = (float*)d_out;

    cudaFuncSetAttribute(lgm_gemm_kernel,
                         cudaFuncAttributeMaxDynamicSharedMemorySize, SMEM_TOTAL);

    precompute_kernel<<<C_CLS, 256>>>(means, vars_, out);
    lgm_gemm_kernel<<<B_BATCH / BM, 256, SMEM_TOTAL>>>(feat, labels, out);
}

// round 6
// speedup vs baseline: 3.3440x; 1.0221x over previous
#include <cuda_runtime.h>
#include <cuda_bf16.h>
#include <cstdint>

// LGMLoss on GB300 — Round 6: cp.async.bulk B pipeline (pre-swizzled GMEM),
// BM=32/grid=64 HMMA GEMM, fully fused loss.
// D[2048x256] = A'[2048x512] @ B'[256x512]^T, bf16 in / fp32 acc.

#define B_BATCH 2048
#define C_CLS   256
#define F_DIM   256
#define ALPHA_F 0.1f
#define EPS_F   1e-8f

#define BM      32
#define NCHUNK  4              // K split: 4 chunks of 128 bf16 (64 features)
#define STR     272            // A smem row stride (256B + 16 pad)
#define B_CHUNK_BYTES 65536    // 256 rows x 256B

// ---------------- device scratch ----------------
// B' pre-swizzled, chunk-major: [4][256 rows][64 words]; word = bf16x2 (iv, -2m*iv)
__device__ uint32_t g_Bchunks[NCHUNK * C_CLS * 64];
__device__ float g_K[C_CLS];
__device__ float g_invden[C_CLS];

// ---------------- helpers ----------------
__device__ __forceinline__ uint32_t smem_u32(const void* p) {
    uint32_t a;
    asm("{ .reg .u64 t; cvta.to.shared.u64 t, %1; cvt.u32.u64 %0, t; }"
        : "=r"(a) : "l"(p));
    return a;
}
__device__ __forceinline__ void ldmatrix_x4(uint32_t* r, uint32_t addr) {
    asm volatile("ldmatrix.sync.aligned.m8n8.x4.shared.b16 {%0,%1,%2,%3}, [%4];"
                 : "=r"(r[0]), "=r"(r[1]), "=r"(r[2]), "=r"(r[3]) : "r"(addr));
}
__device__ __forceinline__ void mma16816(float* d, const uint32_t* a,
                                         uint32_t b0, uint32_t b1) {
    asm volatile(
        "mma.sync.aligned.m16n8k16.row.col.f32.bf16.bf16.f32 "
        "{%0,%1,%2,%3}, {%4,%5,%6,%7}, {%8,%9}, {%0,%1,%2,%3};"
        : "+f"(d[0]), "+f"(d[1]), "+f"(d[2]), "+f"(d[3])
        : "r"(a[0]), "r"(a[1]), "r"(a[2]), "r"(a[3]), "r"(b0), "r"(b1));
}
__device__ __forceinline__ uint32_t pack_pair(float x) {
    __nv_bfloat162 p = __floats2bfloat162_rn(x * x, x);   // (x^2, x)
    return *(uint32_t*)&p;
}
#define MBAR_INIT(a, n) \
    asm volatile("mbarrier.init.shared.b64 [%0], %1;" :: "r"(a), "r"(n) : "memory")
#define MBAR_EXPECT_TX(a, tx) \
    asm volatile("mbarrier.arrive.expect_tx.shared.b64 _, [%0], %1;" \
                 :: "r"(a), "r"(tx) : "memory")
#define MBAR_WAIT(a, ph) do { \
    asm volatile("{ .reg .pred P; WL%=: mbarrier.try_wait.parity.acquire.cta.shared::cta.b64 P, [%0], %1, 0x989680;" \
                 " @P bra WD%=; bra WL%=; WD%=: }" :: "r"(a), "r"(ph) : "memory"); \
} while (0)
__device__ __forceinline__ void bulk_copy(uint32_t dst, const void* src,
                                          uint32_t bytes, uint32_t mbar) {
    asm volatile(
        "cp.async.bulk.shared::cluster.global.mbarrier::complete_tx::bytes "
        "[%0], [%1], %2, [%3];"
        :: "r"(dst), "l"(src), "r"(bytes), "r"(mbar) : "memory");
}

// ---------------------------------------------------------------------------
// Kernel 1: per-class precompute -> swizzled B chunks, K[c], invden[c],
// plus means/vars passthrough. grid = 256, block = 256 (t = feature).
// ---------------------------------------------------------------------------
__global__ __launch_bounds__(256) void precompute_kernel(
    const float* __restrict__ means,
    const float* __restrict__ vars_,
    float* __restrict__ out) {
    int c = blockIdx.x;
    int t = threadIdx.x;
    float v = vars_[c * F_DIM + t];
    float m = means[c * F_DIM + t];
    float iv = 1.0f / (v + EPS_F);
    __nv_bfloat162 pr2 = __floats2bfloat162_rn(iv, -2.0f * m * iv);
    // chunk-major, seg-swizzled store: pair t -> chunk t>>6, pair p=t&63
    {
        int ci = t >> 6, p = t & 63;
        int w = ci * (C_CLS * 64) + c * 64 + ((((p >> 2) ^ (c & 7)) << 2) | (p & 3));
        g_Bchunks[w] = *(uint32_t*)&pr2;
    }
    // passthrough outputs
    out[B_BATCH + c * F_DIM + t] = m;
    out[B_BATCH + C_CLS * F_DIM + c * F_DIM + t] = v;

    float ks = m * m * iv;
    float pr = v;
    #pragma unroll
    for (int o = 16; o > 0; o >>= 1) {
        ks += __shfl_xor_sync(0xffffffffu, ks, o);
        pr *= __shfl_xor_sync(0xffffffffu, pr, o);
    }
    __shared__ float wsum[8], wprod[8];
    int w = t >> 5, l = t & 31;
    if (l == 0) { wsum[w] = ks; wprod[w] = pr; }
    __syncthreads();
    if (t == 0) {
        float K = 0.0f, det = 1.0f;
        #pragma unroll
        for (int i = 0; i < 8; i++) { K += wsum[i]; det *= wprod[i]; }
        g_K[c] = K;
        g_invden[c] = 1.0f / (det * det + EPS_F);
    }
}

// ---------------------------------------------------------------------------
// Kernel 2: fused bf16 HMMA GEMM + prob/loss epilogue.
// grid = 64 CTAs (BM=32 rows, all 256 cols), 256 threads (8 warps).
// Warp w: cols [w*32, w*32+32), rows 0..31 (2 m16 tiles x 4 n8 tiles).
// Dynamic smem:
//   0: sK(1K) | 1024: sInv(1K) | 2048: sPS(1K)+sPP(1K) | 4096: mbar[2]
//   4608: A bufs 2 x 8704 | 22016: B bufs 2 x 65536   total 153088
// ---------------------------------------------------------------------------
#define SM_KOFF 0
#define SM_IOFF 1024
#define SM_RED  2048
#define SM_MBAR 4096
#define SM_A    4608
#define A_BUFSZ 8704
#define SM_B    22016
#define SMEM_TOTAL 153088

__global__ __launch_bounds__(256, 1) void lgm_gemm_kernel(
    const float* __restrict__ feat,
    const int* __restrict__ labels,
    float* __restrict__ out) {
    extern __shared__ char smem[];
    const int tid  = threadIdx.x;
    const int wid  = tid >> 5;
    const int lane = tid & 31;
    const int bRow0 = blockIdx.x * BM;
    const uint32_t sbase = smem_u32(smem);

    float* sK   = (float*)(smem + SM_KOFF);
    float* sInv = (float*)(smem + SM_IOFF);
    float* sPS  = (float*)(smem + SM_RED);          // [32 rows][8 warps]
    float* sPP  = sPS + 256;
    sK[tid]   = g_K[tid];
    sInv[tid] = g_invden[tid];
    if (tid == 0) {
        MBAR_INIT(sbase + SM_MBAR, 1);
        MBAR_INIT(sbase + SM_MBAR + 8, 1);
    }

    const float4* featv = (const float4*)feat;      // 64 float4 per row

    // A: 32 rows x 16 float4 per chunk = 512 segs; 2 per thread
    const int ar = tid >> 3, as = tid & 7;
    float4 aReg[2];
    auto fetchA = [&](int ci) {
        const float4* base = featv + (size_t)(bRow0 + ar) * 64 + ci * 16;
        aReg[0] = base[as];
        aReg[1] = base[as + 8];
    };
    auto storeA = [&](int buf) {
        char* sA = smem + SM_A + buf * A_BUFSZ + ar * STR;
        #pragma unroll
        for (int u = 0; u < 2; u++) {
            uint4 w;
            w.x = pack_pair(aReg[u].x); w.y = pack_pair(aReg[u].y);
            w.z = pack_pair(aReg[u].z); w.w = pack_pair(aReg[u].w);
            *(uint4*)(sA + (as + u * 8) * 16) = w;
        }
    };
    auto issueB = [&](int ci) {
        uint32_t mb = sbase + SM_MBAR + (ci & 1) * 8;
        MBAR_EXPECT_TX(mb, B_CHUNK_BYTES);
        bulk_copy(sbase + SM_B + (ci & 1) * B_CHUNK_BYTES,
                  g_Bchunks + ci * (C_CLS * 64), B_CHUNK_BYTES, mb);
    };

    float acc[2][4][4] = {};

    fetchA(0);
    __syncthreads();          // mbarrier init visible before bulk issue
    if (tid == 0) { issueB(0); issueB(1); }
    storeA(0);
    __syncthreads();          // A(0) visible

    int ph0 = 0, ph1 = 0;
    #pragma unroll
    for (int ci = 0; ci < NCHUNK; ci++) {
        const int buf = ci & 1;
        if (ci + 1 < NCHUNK) fetchA(ci + 1);
        if (buf == 0) { MBAR_WAIT(sbase + SM_MBAR, ph0); ph0 ^= 1; }
        else          { MBAR_WAIT(sbase + SM_MBAR + 8, ph1); ph1 ^= 1; }

        const uint32_t sAu = sbase + SM_A + buf * A_BUFSZ;
        const uint32_t sBu = sbase + SM_B + buf * B_CHUNK_BYTES;
        #pragma unroll
        for (int ks = 0; ks < 8; ks++) {            // 8 x k16 per chunk
            uint32_t a[2][4], b[2][4];
            #pragma unroll
            for (int mt = 0; mt < 2; mt++) {
                ldmatrix_x4(a[mt], sAu + (uint32_t)(mt * 16 + (lane & 15)) * STR
                                  + (uint32_t)(ks * 32 + ((lane >> 4) & 1) * 16));
            }
            #pragma unroll
            for (int nt16 = 0; nt16 < 2; nt16++) {
                int brow = wid * 32 + nt16 * 16 + (lane & 7) + ((lane >> 4) & 1) * 8;
                int bseg = ks * 2 + ((lane >> 3) & 1);
                ldmatrix_x4(b[nt16], sBu + (uint32_t)(brow * 256
                                      + ((bseg ^ (brow & 7)) << 4)));
            }
            #pragma unroll
            for (int mt = 0; mt < 2; mt++) {
                #pragma unroll
                for (int nt = 0; nt < 4; nt++) {
                    mma16816(acc[mt][nt], a[mt],
                             b[nt >> 1][(nt & 1) * 2],
                             b[nt >> 1][(nt & 1) * 2 + 1]);
                }
            }
        }
        if (ci + 1 < NCHUNK) storeA(buf ^ 1);
        __syncthreads();       // A(ci+1) visible; B buf fully consumed
        if (ci + 2 < NCHUNK && tid == 0) issueB(ci + 2);
    }

    // ---------------- epilogue ----------------
    const int r0 = lane >> 2;
    int lbls[2][2];
    #pragma unroll
    for (int mt = 0; mt < 2; mt++) {
        lbls[mt][0] = labels[bRow0 + mt * 16 + r0];
        lbls[mt][1] = labels[bRow0 + mt * 16 + r0 + 8];
    }
    float sums[2][2] = {{0.f,0.f},{0.f,0.f}};
    float pls [2][2] = {{0.f,0.f},{0.f,0.f}};
    #pragma unroll
    for (int nt = 0; nt < 4; nt++) {
        int c0 = wid * 32 + nt * 8 + (lane & 3) * 2;
        int c1 = c0 + 1;
        float k0 = sK[c0], k1 = sK[c1];
        float i0 = sInv[c0], i1 = sInv[c1];
        #pragma unroll
        for (int mt = 0; mt < 2; mt++) {
            #pragma unroll
            for (int h = 0; h < 2; h++) {
                int lbl = lbls[mt][h];
                float d0 = 0.5f * (acc[mt][nt][h * 2 + 0] + k0);
                float d1 = 0.5f * (acc[mt][nt][h * 2 + 1] + k1);
                if (c0 == lbl) d0 *= (1.0f + ALPHA_F);
                if (c1 == lbl) d1 *= (1.0f + ALPHA_F);
                float p0 = __expf(-d0) * i0;
                float p1 = __expf(-d1) * i1;
                sums[mt][h] += p0 + p1;
                if (c0 == lbl) pls[mt][h] += p0;
                if (c1 == lbl) pls[mt][h] += p1;
            }
        }
    }
    #pragma unroll
    for (int o = 1; o < 4; o <<= 1) {
        #pragma unroll
        for (int mt = 0; mt < 2; mt++) {
            #pragma unroll
            for (int h = 0; h < 2; h++) {
                sums[mt][h] += __shfl_xor_sync(0xffffffffu, sums[mt][h], o);
                pls [mt][h] += __shfl_xor_sync(0xffffffffu, pls [mt][h], o);
            }
        }
    }
    if ((lane & 3) == 0) {
        #pragma unroll
        for (int mt = 0; mt < 2; mt++) {
            #pragma unroll
            for (int h = 0; h < 2; h++) {
                int rloc = mt * 16 + r0 + h * 8;
                sPS[rloc * 8 + wid] = sums[mt][h];
                sPP[rloc * 8 + wid] = pls[mt][h];
            }
        }
    }
    __syncthreads();
    if (tid < BM) {
        float s = 0.f, pl = 0.f;
        #pragma unroll
        for (int w = 0; w < 8; w++) {
            s  += sPS[tid * 8 + w];
            pl += sPP[tid * 8 + w];
        }
        out[bRow0 + tid] = -logf(pl / (s + EPS_F) + EPS_F);
    }
}

// ---------------------------------------------------------------------------
extern "C" void kernel_launch(void* const* d_in, const int* in_sizes, int n_in,
                              void* d_out, int out_size) {
    const float* feat   = (const float*)d_in[0];
    const int*   labels = (const int*)d_in[1];
    const float* means  = (const float*)d_in[2];
    const float* vars_  = (const float*)d_in[3];
    float* out = (float*)d_out;

    cudaFuncSetAttribute(lgm_gemm_kernel,
                         cudaFuncAttributeMaxDynamicSharedMemorySize, SMEM_TOTAL);

    precompute_kernel<<<C_CLS, 256>>>(means, vars_, out);
    lgm_gemm_kernel<<<B_BATCH / BM, 256, SMEM_TOTAL>>>(feat, labels, out);
}

// round 7
// speedup vs baseline: 3.9564x; 1.1831x over previous
#include <cuda_runtime.h>
#include <cuda_bf16.h>
#include <cstdint>

// LGMLoss on GB300 — Round 7: single fused kernel. 128 co-resident CTAs,
// device-wide epoch barrier between per-class precompute and HMMA GEMM.
// D[2048x256] = A'[2048x512] @ B'[256x512]^T, bf16 in / fp32 acc.

#define B_BATCH 2048
#define C_CLS   256
#define F_DIM   256
#define ALPHA_F 0.1f
#define EPS_F   1e-8f

#define BM      16
#define NCHUNK  4              // K split: 4 chunks of 128 bf16 (64 features)
#define STR     272            // A smem row stride (256B + 16 pad)
#define B_CHUNK_BYTES 65536    // 256 rows x 256B

// ---------------- device scratch ----------------
// B' pre-swizzled, chunk-major: [4][256 rows][64 words]; word = bf16x2 (iv, -2m*iv)
__device__ uint32_t g_Bchunks[NCHUNK * C_CLS * 64];
__device__ float g_K[C_CLS];
__device__ float g_invden[C_CLS];
__device__ unsigned int g_bar;   // monotonic epoch barrier (never reset)

// ---------------- helpers ----------------
__device__ __forceinline__ uint32_t smem_u32(const void* p) {
    uint32_t a;
    asm("{ .reg .u64 t; cvta.to.shared.u64 t, %1; cvt.u32.u64 %0, t; }"
        : "=r"(a) : "l"(p));
    return a;
}
__device__ __forceinline__ void ldmatrix_x4(uint32_t* r, uint32_t addr) {
    asm volatile("ldmatrix.sync.aligned.m8n8.x4.shared.b16 {%0,%1,%2,%3}, [%4];"
                 : "=r"(r[0]), "=r"(r[1]), "=r"(r[2]), "=r"(r[3]) : "r"(addr));
}
__device__ __forceinline__ void mma16816(float* d, const uint32_t* a,
                                         uint32_t b0, uint32_t b1) {
    asm volatile(
        "mma.sync.aligned.m16n8k16.row.col.f32.bf16.bf16.f32 "
        "{%0,%1,%2,%3}, {%4,%5,%6,%7}, {%8,%9}, {%0,%1,%2,%3};"
        : "+f"(d[0]), "+f"(d[1]), "+f"(d[2]), "+f"(d[3])
        : "r"(a[0]), "r"(a[1]), "r"(a[2]), "r"(a[3]), "r"(b0), "r"(b1));
}
__device__ __forceinline__ uint32_t pack_pair(float x) {
    __nv_bfloat162 p = __floats2bfloat162_rn(x * x, x);   // (x^2, x)
    return *(uint32_t*)&p;
}
#define MBAR_INIT(a, n) \
    asm volatile("mbarrier.init.shared.b64 [%0], %1;" :: "r"(a), "r"(n) : "memory")
#define MBAR_EXPECT_TX(a, tx) \
    asm volatile("mbarrier.arrive.expect_tx.shared.b64 _, [%0], %1;" \
                 :: "r"(a), "r"(tx) : "memory")
#define MBAR_WAIT(a, ph) do { \
    asm volatile("{ .reg .pred P; WL%=: mbarrier.try_wait.parity.acquire.cta.shared::cta.b64 P, [%0], %1, 0x989680;" \
                 " @P bra WD%=; bra WL%=; WD%=: }" :: "r"(a), "r"(ph) : "memory"); \
} while (0)
__device__ __forceinline__ void bulk_copy(uint32_t dst, const void* src,
                                          uint32_t bytes, uint32_t mbar) {
    asm volatile(
        "cp.async.bulk.shared::cluster.global.mbarrier::complete_tx::bytes "
        "[%0], [%1], %2, [%3];"
        :: "r"(dst), "l"(src), "r"(bytes), "r"(mbar) : "memory");
}

// ---------------------------------------------------------------------------
// Fused kernel. grid = 128 CTAs x 256 threads (8 warps), 143KB smem -> 1/SM,
// all 128 CTAs co-resident => software grid barrier is safe.
// Smem layout (bytes):
//   0: sK(1K) | 1024: sInv(1K) | 2048: sRed(1K, reused) | 3072: mbar[2]
//   3584: A bufs 2 x 4352 | 12288: B bufs 2 x 65536   total 143360
// ---------------------------------------------------------------------------
#define SM_KOFF 0
#define SM_IOFF 1024
#define SM_RED  2048
#define SM_MBAR 3072
#define SM_A    3584
#define A_BUFSZ 4352
#define SM_B    12288
#define SMEM_TOTAL 143360

__global__ __launch_bounds__(256, 1) void lgm_fused_kernel(
    const float* __restrict__ feat,
    const int* __restrict__ labels,
    const float* __restrict__ means,
    const float* __restrict__ vars_,
    float* __restrict__ out) {
    extern __shared__ char smem[];
    const int tid  = threadIdx.x;
    const int wid  = tid >> 5;
    const int lane = tid & 31;
    const int bid  = blockIdx.x;
    const int bRow0 = bid * BM;
    const uint32_t sbase = smem_u32(smem);

    float* sK   = (float*)(smem + SM_KOFF);
    float* sInv = (float*)(smem + SM_IOFF);
    float* sRed = (float*)(smem + SM_RED);
    float* sPS  = sRed;                       // epilogue reuse: [16 rows][8 warps]
    float* sPP  = sRed + 128;

    if (tid == 0) {
        MBAR_INIT(sbase + SM_MBAR, 1);
        MBAR_INIT(sbase + SM_MBAR + 8, 1);
    }

    const float4* featv = (const float4*)feat;      // 64 float4 per row
    // A: 16 rows x 16 segs per chunk = 256 segs; 1 per thread
    const int ar = tid >> 4, as = tid & 15;
    float4 aReg;
    auto fetchA = [&](int ci) {
        aReg = featv[(size_t)(bRow0 + ar) * 64 + ci * 16 + as];
    };
    auto storeA = [&](int buf) {
        uint4 w;
        w.x = pack_pair(aReg.x); w.y = pack_pair(aReg.y);
        w.z = pack_pair(aReg.z); w.w = pack_pair(aReg.w);
        *(uint4*)(smem + SM_A + buf * A_BUFSZ + ar * STR + as * 16) = w;
    };
    auto issueB = [&](int ci) {
        uint32_t mb = sbase + SM_MBAR + (ci & 1) * 8;
        MBAR_EXPECT_TX(mb, B_CHUNK_BYTES);
        bulk_copy(sbase + SM_B + (ci & 1) * B_CHUNK_BYTES,
                  g_Bchunks + ci * (C_CLS * 64), B_CHUNK_BYTES, mb);
    };

    fetchA(0);        // A LDGs in flight during phase 1

    // ---------------- phase 1: per-class precompute (2 classes per CTA) ----
    {
        const int half = tid >> 7;            // 0/1 -> class
        const int tf   = tid & 127;           // feature pair index (2 feats)
        const int c    = 2 * bid + half;
        float2 mv = ((const float2*)means)[c * 128 + tf];
        float2 vv = ((const float2*)vars_)[c * 128 + tf];
        float iv0 = 1.0f / (vv.x + EPS_F);
        float iv1 = 1.0f / (vv.y + EPS_F);
        __nv_bfloat162 p0 = __floats2bfloat162_rn(iv0, -2.0f * mv.x * iv0);
        __nv_bfloat162 p1 = __floats2bfloat162_rn(iv1, -2.0f * mv.y * iv1);
        // swizzled chunk-major store: feature f=2tf -> chunk f>>6, pair p=f&63
        {
            int f = 2 * tf;
            int ci = f >> 6, p = f & 63;
            int idx = ci * (C_CLS * 64) + c * 64
                    + ((((p >> 2) ^ (c & 7)) << 2) | (p & 3));
            uint2 w;
            w.x = *(uint32_t*)&p0;
            w.y = *(uint32_t*)&p1;
            *(uint2*)&g_Bchunks[idx] = w;     // p even -> consecutive words
        }
        // passthrough outputs
        ((float2*)(out + B_BATCH))[c * 128 + tf] = mv;
        ((float2*)(out + B_BATCH + C_CLS * F_DIM))[c * 128 + tf] = vv;

        float ks = mv.x * mv.x * iv0 + mv.y * mv.y * iv1;
        float pr = vv.x * vv.y;
        #pragma unroll
        for (int o = 16; o > 0; o >>= 1) {
            ks += __shfl_xor_sync(0xffffffffu, ks, o);
            pr *= __shfl_xor_sync(0xffffffffu, pr, o);
        }
        if (lane == 0) { sRed[wid] = ks; sRed[8 + wid] = pr; }
        __syncthreads();
        if (tf == 0) {
            float K = 0.0f, det = 1.0f;
            #pragma unroll
            for (int i = 0; i < 4; i++) {
                K += sRed[half * 4 + i];
                det *= sRed[8 + half * 4 + i];
            }
            g_K[c] = K;
            g_invden[c] = 1.0f / (det * det + EPS_F);
        }
    }
    storeA(0);
    fetchA(1);

    // ---------------- device-wide epoch barrier ----------------
    __syncthreads();
    if (tid == 0) {
        __threadfence();
        unsigned tk = atomicAdd(&g_bar, 1u);
        unsigned target = (tk & ~127u) + 128u;
        unsigned cur;
        do {
            asm volatile("ld.acquire.gpu.global.b32 %0, [%1];"
                         : "=r"(cur) : "l"(&g_bar));
        } while (cur < target);
        asm volatile("fence.proxy.async;" ::: "memory");
        issueB(0); issueB(1);
    }
    __syncthreads();
    __threadfence();

    // per-class constants into smem (after barrier: g_K/g_invden valid)
    sK[tid]   = g_K[tid];
    sInv[tid] = g_invden[tid];

    // ---------------- phase 2: GEMM mainloop ----------------
    float acc[4][4] = {};
    int ph0 = 0, ph1 = 0;
    #pragma unroll
    for (int ci = 0; ci < NCHUNK; ci++) {
        const int buf = ci & 1;
        if (buf == 0) { MBAR_WAIT(sbase + SM_MBAR, ph0); ph0 ^= 1; }
        else          { MBAR_WAIT(sbase + SM_MBAR + 8, ph1); ph1 ^= 1; }

        const uint32_t sAu = sbase + SM_A + buf * A_BUFSZ;
        const uint32_t sBu = sbase + SM_B + buf * B_CHUNK_BYTES;
        #pragma unroll
        for (int ks = 0; ks < 8; ks++) {            // 8 x k16 per chunk
            uint32_t a[4], b[2][4];
            ldmatrix_x4(a, sAu + (uint32_t)(lane & 15) * STR
                           + (uint32_t)(ks * 32 + ((lane >> 4) & 1) * 16));
            #pragma unroll
            for (int nt16 = 0; nt16 < 2; nt16++) {
                int brow = wid * 32 + nt16 * 16 + (lane & 7) + ((lane >> 4) & 1) * 8;
                int bseg = ks * 2 + ((lane >> 3) & 1);
                ldmatrix_x4(b[nt16], sBu + (uint32_t)(brow * 256
                                      + ((bseg ^ (brow & 7)) << 4)));
            }
            #pragma unroll
            for (int nt = 0; nt < 4; nt++) {
                mma16816(acc[nt], a, b[nt >> 1][(nt & 1) * 2],
                                     b[nt >> 1][(nt & 1) * 2 + 1]);
            }
        }
        if (ci + 1 < NCHUNK) storeA(buf ^ 1);       // chunk ci+1 (already fetched)
        __syncthreads();
        if (ci + 2 < NCHUNK) fetchA(ci + 2);
        if (tid == 0 && ci + 2 < NCHUNK) issueB(ci + 2);
    }

    // ---------------- epilogue: prob + fused loss ----------------
    const int r0 = lane >> 2;
    const int lbl0 = labels[bRow0 + r0];
    const int lbl1 = labels[bRow0 + r0 + 8];
    float s0 = 0.f, s1 = 0.f, pl0 = 0.f, pl1 = 0.f;
    #pragma unroll
    for (int nt = 0; nt < 4; nt++) {
        int c0 = wid * 32 + nt * 8 + (lane & 3) * 2;
        int c1 = c0 + 1;
        float k0 = sK[c0], k1 = sK[c1];
        float i0 = sInv[c0], i1 = sInv[c1];
        {
            float d0 = 0.5f * (acc[nt][0] + k0);
            float d1 = 0.5f * (acc[nt][1] + k1);
            if (c0 == lbl0) d0 *= (1.0f + ALPHA_F);
            if (c1 == lbl0) d1 *= (1.0f + ALPHA_F);
            float p0 = __expf(-d0) * i0;
            float p1 = __expf(-d1) * i1;
            s0 += p0 + p1;
            if (c0 == lbl0) pl0 += p0;
            if (c1 == lbl0) pl0 += p1;
        }
        {
            float d0 = 0.5f * (acc[nt][2] + k0);
            float d1 = 0.5f * (acc[nt][3] + k1);
            if (c0 == lbl1) d0 *= (1.0f + ALPHA_F);
            if (c1 == lbl1) d1 *= (1.0f + ALPHA_F);
            float p0 = __expf(-d0) * i0;
            float p1 = __expf(-d1) * i1;
            s1 += p0 + p1;
            if (c0 == lbl1) pl1 += p0;
            if (c1 == lbl1) pl1 += p1;
        }
    }
    #pragma unroll
    for (int o = 1; o < 4; o <<= 1) {
        s0  += __shfl_xor_sync(0xffffffffu, s0, o);
        s1  += __shfl_xor_sync(0xffffffffu, s1, o);
        pl0 += __shfl_xor_sync(0xffffffffu, pl0, o);
        pl1 += __shfl_xor_sync(0xffffffffu, pl1, o);
    }
    if ((lane & 3) == 0) {
        sPS[r0 * 8 + wid]       = s0;
        sPS[(r0 + 8) * 8 + wid] = s1;
        sPP[r0 * 8 + wid]       = pl0;
        sPP[(r0 + 8) * 8 + wid] = pl1;
    }
    __syncthreads();
    if (tid < BM) {
        float s = 0.f, pl = 0.f;
        #pragma unroll
        for (int w = 0; w < 8; w++) {
            s  += sPS[tid * 8 + w];
            pl += sPP[tid * 8 + w];
        }
        out[bRow0 + tid] = -logf(pl / (s + EPS_F) + EPS_F);
    }
}

// ---------------------------------------------------------------------------
extern "C" void kernel_launch(void* const* d_in, const int* in_sizes, int n_in,
                              void* d_out, int out_size) {
    const float* feat   = (const float*)d_in[0];
    const int*   labels = (const int*)d_in[1];
    const float* means  = (const float*)d_in[2];
    const float* vars_  = (const float*)d_in[3];
    float* out = (float*)d_out;

    cudaFuncSetAttribute(lgm_fused_kernel,
                         cudaFuncAttributeMaxDynamicSharedMemorySize, SMEM_TOTAL);

    lgm_fused_kernel<<<B_BATCH / BM, 256, SMEM_TOTAL>>>(
        feat, labels, means, vars_, out);
}